// round 14
// baseline (speedup 1.0000x reference)
#include <cuda_runtime.h>
#include <cuda_fp16.h>
#include <cstdint>

#define BATCH 8192
#define SEQ   40
#define HID   256
#define VOCAB 128

// ===========================================================================
// Global scratch (no cudaMalloc allowed)
// ===========================================================================
// A fragments (h state, single fp16 plane), ping-pong.
// block = grp*16 + kc*2 + ks; grp = batch/16. 32 lanes x uint4.
__device__ __align__(16) uint4 g_Afrag[2][8192][32];
// B fragments (Wh fp16). block = (jt*4+jw)*32 + it*2 + gp.
__device__ __align__(16) uint4 g_Bfrag[1024][32];
__device__ float g_c[BATCH * HID];
__device__ float g_Wxb[128 * 1024];
__device__ float g_hfin[BATCH * HID];
__device__ int   g_inT[SEQ * BATCH];

__device__ __forceinline__ uint32_t smem_to_u32(const void* p) {
    uint32_t a;
    asm("{ .reg .u64 tmp; cvta.to.shared.u64 tmp, %1; cvt.u32.u64 %0, tmp; }"
        : "=r"(a) : "l"(p));
    return a;
}

#define CP_ASYNC16(dst, src) \
    asm volatile("cp.async.cg.shared.global [%0], [%1], 16;" \
        :: "r"(dst), "l"(src) : "memory")
#define CP_COMMIT() asm volatile("cp.async.commit_group;" ::: "memory")
#define CP_WAIT0()  asm volatile("cp.async.wait_group 0;" ::: "memory")

#define LDS128(r0, r1, r2, r3, addr) \
    asm volatile("ld.shared.v4.b32 {%0,%1,%2,%3}, [%4];" \
        : "=r"(r0), "=r"(r1), "=r"(r2), "=r"(r3) : "r"(addr))

#define MMA16816(d, a, b0, b1) \
    asm volatile("mma.sync.aligned.m16n8k16.row.col.f32.f16.f16.f32 " \
        "{%0,%1,%2,%3}, {%4,%5,%6,%7}, {%8,%9}, {%0,%1,%2,%3};" \
        : "+f"((d)[0]), "+f"((d)[1]), "+f"((d)[2]), "+f"((d)[3]) \
        : "r"((a)[0]), "r"((a)[1]), "r"((a)[2]), "r"((a)[3]), \
          "r"(b0), "r"(b1))

#define PDL_LAUNCH_DEPENDENTS() \
    asm volatile("griddepcontrol.launch_dependents;")
#define PDL_WAIT() \
    asm volatile("griddepcontrol.wait;" ::: "memory")
#define PREFETCH_L1(p) \
    asm volatile("prefetch.global.L1 [%0];" :: "l"(p))

__device__ __forceinline__ float sigf(float x) {
    return 1.0f / (1.0f + __expf(-x));
}
__device__ __forceinline__ float tanh_(float x) {
    float ax = fabsf(x);
    float e  = __expf(-2.0f * ax);
    float r  = (1.0f - e) / (1.0f + e);
    return copysignf(r, x);
}

// ===========================================================================
// Fused prep: init state + Wh->B frags + Wx+b + input transpose (1 launch)
// ===========================================================================
__global__ void prep_all_kernel(const int*   __restrict__ inputs,
                                const float* __restrict__ Wh,
                                const float* __restrict__ Wx,
                                const float* __restrict__ bias) {
    int i = blockIdx.x * blockDim.x + threadIdx.x;

    ((float4*)g_c)[i] = make_float4(0.f, 0.f, 0.f, 0.f);

    if (i < 262144)
        ((uint4*)g_Afrag[0])[i] = make_uint4(0, 0, 0, 0);

    if (i < 262144) {
        int k = i >> 10, col = i & 1023;
        __half hi = __float2half(Wh[i]);
        int gate = col >> 8, j = col & 255;
        int jt = j >> 5, jw = (j >> 3) & 3, nl = j & 7;
        int kc = k >> 5, ks = (k >> 4) & 1, kk = k & 15;
        int gp = gate >> 1, gs = gate & 1;
        int lane = nl * 4 + ((kk & 7) >> 1);
        int reg  = kk >> 3;
        int hp   = kk & 1;
        int block = (jt * 4 + jw) * 32 + (kc * 2 + ks) * 2 + gp;
        ((__half*)g_Bfrag)[((size_t)block * 32 + lane) * 8 + gs * 4 + reg * 2 + hp] = hi;
    }

    if (i < 131072)
        g_Wxb[i] = Wx[i] + bias[i & 1023];

    if (i < SEQ * BATCH) {
        int b = i / SEQ, tt = i - b * SEQ;
        g_inT[tt * BATCH + b] = inputs[i];
    }
}

// ===========================================================================
// LSTM step (r10 loop + PDL). Pre-wait: indices, chars, B iter0, Wxb L1
// prefetch (all stable data). Post-wait: A cp.async, mainloop, epilogue.
// CTA 256 thr = 8 warps (2 mw x 4 jw); warp tile M=32 x (4g x 8j).
// ===========================================================================
#define SMEM_TOTAL 32768

__global__ __launch_bounds__(256, 3) void lstm_step_kernel(int t) {
    // allow next step's CTAs to spin up immediately (their pre-wait code
    // only reads prep-stable data)
    PDL_LAUNCH_DEPENDENTS();

    extern __shared__ __align__(16) unsigned char smem[];
    const uint32_t sA = smem_to_u32(smem);
    const int tid  = threadIdx.x;
    const int lane = tid & 31, wid = tid >> 5;
    const int mw = wid >> 2;          // 0..1
    const int jw = wid & 3;           // 0..3
    const int bx = blockIdx.x;        // 0..127
    const int jt = blockIdx.y;        // 0..7

    const int gq = lane >> 2, t4 = lane & 3;
    const int jcol = jt * 32 + jw * 8 + t4 * 2;

    // ---- pre-wait: chars (stable)
    int ch[2][2];
#pragma unroll
    for (int mt = 0; mt < 2; mt++)
#pragma unroll
        for (int rr = 0; rr < 2; rr++)
            ch[mt][rr] = g_inT[t * BATCH + bx * 64 + mw * 32 + mt * 16 + gq + rr * 8];

    // ---- pre-wait: B iter 0 (stable)
    const uint4* __restrict__ Bp = &g_Bfrag[(jt * 4 + jw) * 32][lane];
    uint4 bv0 = Bp[0], bv1 = Bp[32];

    // ---- pre-wait: warm L1 with this thread's Wxb rows (stable)
#pragma unroll
    for (int mt = 0; mt < 2; mt++)
#pragma unroll
        for (int rr = 0; rr < 2; rr++) {
            const float* wrow = g_Wxb + (size_t)ch[mt][rr] * 1024;
#pragma unroll
            for (int g = 0; g < 4; g++)
                PREFETCH_L1(&wrow[g * 256 + jcol]);
        }

    // ---- previous step complete from here on
    PDL_WAIT();

    // ---- stage A tile (64 blocks = 4 batch-groups) into SMEM: 2048 uint4
    {
        const uint4* Asrc = &g_Afrag[t & 1][bx * 64][0];
#pragma unroll
        for (int i = 0; i < 8; i++)
            CP_ASYNC16(sA + tid * 16 + i * 4096,
                       (const char*)(Asrc + i * 256 + tid));
        CP_COMMIT();
    }
    CP_WAIT0();
    __syncthreads();

    float acc[2][4][4];
#pragma unroll
    for (int mt = 0; mt < 2; mt++)
#pragma unroll
        for (int g = 0; g < 4; g++)
#pragma unroll
            for (int e = 0; e < 4; e++) acc[mt][g][e] = 0.0f;

    const uint32_t aoff0 = sA + (mw * 2 + 0) * 16 * 512 + lane * 16;
    const uint32_t aoff1 = sA + (mw * 2 + 1) * 16 * 512 + lane * 16;

#pragma unroll 4
    for (int it = 0; it < 16; it++) {
        uint4 bn0, bn1;
        if (it < 15) {
            const uint4* p = Bp + (it + 1) * 64;
            bn0 = p[0]; bn1 = p[32];
        } else {
            bn0 = bv0; bn1 = bv1;
        }

        uint32_t ah[2][4];
        {
            uint32_t o = it * 512;
            LDS128(ah[0][0], ah[0][1], ah[0][2], ah[0][3], aoff0 + o);
            LDS128(ah[1][0], ah[1][1], ah[1][2], ah[1][3], aoff1 + o);
        }

#pragma unroll
        for (int mt = 0; mt < 2; mt++) {
            MMA16816(acc[mt][0], ah[mt], bv0.x, bv0.y);
            MMA16816(acc[mt][1], ah[mt], bv0.z, bv0.w);
            MMA16816(acc[mt][2], ah[mt], bv1.x, bv1.y);
            MMA16816(acc[mt][3], ah[mt], bv1.z, bv1.w);
        }
        bv0 = bn0; bv1 = bn1;
    }

    // ---- Epilogue: z = acc + Wxb[char] -> gates -> c; h stored as A-frags.
    const int blk_base = jt * 2 + (jw >> 1);
    uint32_t* __restrict__ Aout = (uint32_t*)g_Afrag[(t + 1) & 1];

#pragma unroll
    for (int mt = 0; mt < 2; mt++) {
        const int grp = bx * 4 + mw * 2 + mt;
#pragma unroll
        for (int rr = 0; rr < 2; rr++) {
            const int b = bx * 64 + mw * 32 + mt * 16 + gq + rr * 8;
            const float* wrow = g_Wxb + (size_t)ch[mt][rr] * 1024;
            float2 wx2[4];
#pragma unroll
            for (int g = 0; g < 4; g++)
                wx2[g] = *(const float2*)&wrow[g * 256 + jcol];
            float2 c2 = *(const float2*)&g_c[(size_t)b * HID + jcol];

            float cn[2], hn[2];
#pragma unroll
            for (int e = 0; e < 2; e++) {
                float zi = acc[mt][0][rr * 2 + e] + (e ? wx2[0].y : wx2[0].x);
                float zf = acc[mt][1][rr * 2 + e] + (e ? wx2[1].y : wx2[1].x);
                float zg = acc[mt][2][rr * 2 + e] + (e ? wx2[2].y : wx2[2].x);
                float zo = acc[mt][3][rr * 2 + e] + (e ? wx2[3].y : wx2[3].x);
                float ig = sigf(zi), fg = sigf(zf);
                float gg = tanh_(zg), og = sigf(zo);
                float cold = e ? c2.y : c2.x;
                float cc = fg * cold + ig * gg;
                cn[e] = cc;
                hn[e] = og * tanh_(cc);
            }
            *(float2*)&g_c[(size_t)b * HID + jcol] = make_float2(cn[0], cn[1]);

            __half2 phi = __halves2half2(__float2half(hn[0]), __float2half(hn[1]));
            const int reg = rr + 2 * (jw & 1);
            uint32_t idx = (uint32_t)(((grp * 16 + blk_base) * 32 + lane) * 4 + reg);
            Aout[idx] = *(uint32_t*)&phi;

            if (t == SEQ - 1)
                *(float2*)&g_hfin[(size_t)b * HID + jcol] = make_float2(hn[0], hn[1]);
        }
    }
}

// ===========================================================================
// Dense + softmax (reads g_hfin, float)
// ===========================================================================
#define DROWS 8

__global__ __launch_bounds__(128) void dense_softmax_kernel(
    const float* __restrict__ Wd,   // [256, 128]
    const float* __restrict__ bd,   // [128]
    float*       __restrict__ out)  // [BATCH, 128]
{
    const int b0  = blockIdx.x * DROWS;
    const int tid = threadIdx.x;

    __shared__ float hs[DROWS][HID];
    __shared__ float ls[DROWS][VOCAB];

#pragma unroll
    for (int s = 0; s < DROWS * HID / 128; s++) {
        int e = tid + s * 128;
        hs[e >> 8][e & 255] = g_hfin[(size_t)b0 * HID + e];
    }
    __syncthreads();

    float acc[DROWS];
    float bv = bd[tid];
#pragma unroll
    for (int r = 0; r < DROWS; r++) acc[r] = bv;

#pragma unroll 8
    for (int k = 0; k < HID; k++) {
        float w = Wd[k * VOCAB + tid];
#pragma unroll
        for (int r = 0; r < DROWS; r++) acc[r] += hs[r][k] * w;
    }

#pragma unroll
    for (int r = 0; r < DROWS; r++) ls[r][tid] = acc[r];
    __syncthreads();

    const int w = tid >> 5, lane = tid & 31;
#pragma unroll
    for (int rr = 0; rr < 2; rr++) {
        int r = w * 2 + rr;
        float v[4];
        float m = -1e30f;
#pragma unroll
        for (int q = 0; q < 4; q++) {
            v[q] = ls[r][lane + q * 32];
            m = fmaxf(m, v[q]);
        }
#pragma unroll
        for (int o = 16; o > 0; o >>= 1) m = fmaxf(m, __shfl_xor_sync(0xffffffffu, m, o));
        float s = 0.0f;
#pragma unroll
        for (int q = 0; q < 4; q++) {
            v[q] = __expf(v[q] - m);
            s += v[q];
        }
#pragma unroll
        for (int o = 16; o > 0; o >>= 1) s += __shfl_xor_sync(0xffffffffu, s, o);
        float inv = 1.0f / s;
#pragma unroll
        for (int q = 0; q < 4; q++)
            out[(b0 + r) * VOCAB + lane + q * 32] = v[q] * inv;
    }
}

// ===========================================================================
extern "C" void kernel_launch(void* const* d_in, const int* in_sizes, int n_in,
                              void* d_out, int out_size) {
    const int*   inputs = (const int*)d_in[0];
    const float* Wx     = (const float*)d_in[1];
    const float* Wh     = (const float*)d_in[2];
    const float* b      = (const float*)d_in[3];
    const float* Wd     = (const float*)d_in[4];
    const float* bd     = (const float*)d_in[5];
    float*       out    = (float*)d_out;

    cudaFuncSetAttribute(lstm_step_kernel,
                         cudaFuncAttributeMaxDynamicSharedMemorySize, SMEM_TOTAL);

    prep_all_kernel<<<2048, 256>>>(inputs, Wh, Wx, b);

    // step 0: normal launch (must fully wait for prep's B/Wxb/inT writes)
    lstm_step_kernel<<<dim3(128, 8), 256, SMEM_TOTAL>>>(0);

    // steps 1..39: programmatic dependent launch — prologue overlaps the
    // previous step's tail; data ordering enforced by griddepcontrol.wait.
    cudaLaunchAttribute at[1];
    at[0].id = cudaLaunchAttributeProgrammaticStreamSerialization;
    at[0].val.programmaticStreamSerializationAllowed = 1;
    for (int t = 1; t < SEQ; t++) {
        cudaLaunchConfig_t cfg = {};
        cfg.gridDim  = dim3(128, 8);
        cfg.blockDim = dim3(256);
        cfg.dynamicSmemBytes = SMEM_TOTAL;
        cfg.stream = 0;
        cfg.attrs = at;
        cfg.numAttrs = 1;
        cudaLaunchKernelEx(&cfg, lstm_step_kernel, t);
    }

    dense_softmax_kernel<<<BATCH / DROWS, 128>>>(Wd, bd, out);
}

// round 15
// speedup vs baseline: 1.1247x; 1.1247x over previous
#include <cuda_runtime.h>
#include <cuda_fp16.h>
#include <cstdint>

#define BATCH 8192
#define SEQ   40
#define HID   256
#define VOCAB 128

// ===========================================================================
// Global scratch (no cudaMalloc allowed)
// ===========================================================================
// A fragments (h state, single fp16 plane), ping-pong.
// block = grp*16 + kc*2 + ks; grp = batch/16. 32 lanes x uint4.
__device__ __align__(16) uint4 g_Afrag[2][8192][32];
// B fragments (Wh fp16). block = (jt*4+jw)*32 + it*2 + gp.
__device__ __align__(16) uint4 g_Bfrag[1024][32];
__device__ float g_c[BATCH * HID];
__device__ float g_Wxb[128 * 1024];
__device__ float g_hfin[BATCH * HID];
__device__ int   g_inT[SEQ * BATCH];

__device__ __forceinline__ uint32_t smem_to_u32(const void* p) {
    uint32_t a;
    asm("{ .reg .u64 tmp; cvta.to.shared.u64 tmp, %1; cvt.u32.u64 %0, tmp; }"
        : "=r"(a) : "l"(p));
    return a;
}

#define CP_ASYNC16(dst, src) \
    asm volatile("cp.async.cg.shared.global [%0], [%1], 16;" \
        :: "r"(dst), "l"(src) : "memory")
#define CP_COMMIT() asm volatile("cp.async.commit_group;" ::: "memory")
#define CP_WAIT0()  asm volatile("cp.async.wait_group 0;" ::: "memory")

#define LDS128(r0, r1, r2, r3, addr) \
    asm volatile("ld.shared.v4.b32 {%0,%1,%2,%3}, [%4];" \
        : "=r"(r0), "=r"(r1), "=r"(r2), "=r"(r3) : "r"(addr))

#define MMA16816(d, a, b0, b1) \
    asm volatile("mma.sync.aligned.m16n8k16.row.col.f32.f16.f16.f32 " \
        "{%0,%1,%2,%3}, {%4,%5,%6,%7}, {%8,%9}, {%0,%1,%2,%3};" \
        : "+f"((d)[0]), "+f"((d)[1]), "+f"((d)[2]), "+f"((d)[3]) \
        : "r"((a)[0]), "r"((a)[1]), "r"((a)[2]), "r"((a)[3]), \
          "r"(b0), "r"(b1))

__device__ __forceinline__ float sigf(float x) {
    return 1.0f / (1.0f + __expf(-x));
}
__device__ __forceinline__ float tanh_(float x) {
    float ax = fabsf(x);
    float e  = __expf(-2.0f * ax);
    float r  = (1.0f - e) / (1.0f + e);
    return copysignf(r, x);
}

// ===========================================================================
// Fused prep: init state + Wh->B frags + Wx+b + input transpose (1 launch)
// grid 2048 x 256 = 524288 threads
// ===========================================================================
__global__ void prep_all_kernel(const int*   __restrict__ inputs,
                                const float* __restrict__ Wh,
                                const float* __restrict__ Wx,
                                const float* __restrict__ bias) {
    int i = blockIdx.x * blockDim.x + threadIdx.x;

    // init c (524288 float4)
    ((float4*)g_c)[i] = make_float4(0.f, 0.f, 0.f, 0.f);

    // init A-frag buffer 0
    if (i < 262144)
        ((uint4*)g_Afrag[0])[i] = make_uint4(0, 0, 0, 0);

    // Wh -> B fragments (fp16)
    if (i < 262144) {
        int k = i >> 10, col = i & 1023;
        __half hi = __float2half(Wh[i]);
        int gate = col >> 8, j = col & 255;
        int jt = j >> 5, jw = (j >> 3) & 3, nl = j & 7;
        int kc = k >> 5, ks = (k >> 4) & 1, kk = k & 15;
        int gp = gate >> 1, gs = gate & 1;
        int lane = nl * 4 + ((kk & 7) >> 1);
        int reg  = kk >> 3;
        int hp   = kk & 1;
        int block = (jt * 4 + jw) * 32 + (kc * 2 + ks) * 2 + gp;
        ((__half*)g_Bfrag)[((size_t)block * 32 + lane) * 8 + gs * 4 + reg * 2 + hp] = hi;
    }

    // Wx + bias
    if (i < 131072)
        g_Wxb[i] = Wx[i] + bias[i & 1023];

    // transpose chars
    if (i < SEQ * BATCH) {
        int b = i / SEQ, tt = i - b * SEQ;
        g_inT[tt * BATCH + b] = inputs[i];
    }
}

// ===========================================================================
// LSTM step (r10 configuration). Grid (128, 8); CTA 256 thr = 8 warps
// (2 mw x 4 jw); warp tile M=32 x (4g x 8j). Single-pass fp16.
// A tile (64 batch x K = 32KB) staged in SMEM via cp.async; B frags LDG'd
// with register double-buffer. occ 3.
// ===========================================================================
#define SMEM_TOTAL 32768

__global__ __launch_bounds__(256, 3) void lstm_step_kernel(int t) {
    extern __shared__ __align__(16) unsigned char smem[];
    const uint32_t sA = smem_to_u32(smem);
    const int tid  = threadIdx.x;
    const int lane = tid & 31, wid = tid >> 5;
    const int mw = wid >> 2;          // 0..1
    const int jw = wid & 3;           // 0..3
    const int bx = blockIdx.x;        // 0..127
    const int jt = blockIdx.y;        // 0..7

    // ---- stage A tile (64 blocks = 4 batch-groups) into SMEM: 2048 uint4
    {
        const uint4* Asrc = &g_Afrag[t & 1][bx * 64][0];
#pragma unroll
        for (int i = 0; i < 8; i++)
            CP_ASYNC16(sA + tid * 16 + i * 4096,
                       (const char*)(Asrc + i * 256 + tid));
        CP_COMMIT();
    }

    // ---- prefetch chars while A streams
    const int gq = lane >> 2, t4 = lane & 3;
    int ch[2][2];
#pragma unroll
    for (int mt = 0; mt < 2; mt++)
#pragma unroll
        for (int rr = 0; rr < 2; rr++)
            ch[mt][rr] = g_inT[t * BATCH + bx * 64 + mw * 32 + mt * 16 + gq + rr * 8];

    // ---- prefetch B iter 0 (2 blocks: gate pairs)
    const uint4* __restrict__ Bp = &g_Bfrag[(jt * 4 + jw) * 32][lane];
    uint4 bv0 = Bp[0], bv1 = Bp[32];

    CP_WAIT0();
    __syncthreads();

    float acc[2][4][4];
#pragma unroll
    for (int mt = 0; mt < 2; mt++)
#pragma unroll
        for (int g = 0; g < 4; g++)
#pragma unroll
            for (int e = 0; e < 4; e++) acc[mt][g][e] = 0.0f;

    // A smem: block (mw*2+mt)*16 + it, 512B/block
    const uint32_t aoff0 = sA + (mw * 2 + 0) * 16 * 512 + lane * 16;
    const uint32_t aoff1 = sA + (mw * 2 + 1) * 16 * 512 + lane * 16;

#pragma unroll 4
    for (int it = 0; it < 16; it++) {
        uint4 bn0, bn1;
        if (it < 15) {
            const uint4* p = Bp + (it + 1) * 64;
            bn0 = p[0]; bn1 = p[32];
        } else {
            bn0 = bv0; bn1 = bv1;
        }

        uint32_t ah[2][4];
        {
            uint32_t o = it * 512;
            LDS128(ah[0][0], ah[0][1], ah[0][2], ah[0][3], aoff0 + o);
            LDS128(ah[1][0], ah[1][1], ah[1][2], ah[1][3], aoff1 + o);
        }

#pragma unroll
        for (int mt = 0; mt < 2; mt++) {
            MMA16816(acc[mt][0], ah[mt], bv0.x, bv0.y);
            MMA16816(acc[mt][1], ah[mt], bv0.z, bv0.w);
            MMA16816(acc[mt][2], ah[mt], bv1.x, bv1.y);
            MMA16816(acc[mt][3], ah[mt], bv1.z, bv1.w);
        }
        bv0 = bn0; bv1 = bn1;
    }

    // ---- Epilogue: z = acc + Wxb[char] -> gates -> c; h stored as A-frags.
    const int jcol = jt * 32 + jw * 8 + t4 * 2;   // even
    const int blk_base = jt * 2 + (jw >> 1);
    uint32_t* __restrict__ Aout = (uint32_t*)g_Afrag[(t + 1) & 1];

#pragma unroll
    for (int mt = 0; mt < 2; mt++) {
        const int grp = bx * 4 + mw * 2 + mt;
#pragma unroll
        for (int rr = 0; rr < 2; rr++) {
            const int b = bx * 64 + mw * 32 + mt * 16 + gq + rr * 8;
            const float* wrow = g_Wxb + (size_t)ch[mt][rr] * 1024;
            float2 wx2[4];
#pragma unroll
            for (int g = 0; g < 4; g++)
                wx2[g] = *(const float2*)&wrow[g * 256 + jcol];
            float2 c2 = *(const float2*)&g_c[(size_t)b * HID + jcol];

            float cn[2], hn[2];
#pragma unroll
            for (int e = 0; e < 2; e++) {
                float zi = acc[mt][0][rr * 2 + e] + (e ? wx2[0].y : wx2[0].x);
                float zf = acc[mt][1][rr * 2 + e] + (e ? wx2[1].y : wx2[1].x);
                float zg = acc[mt][2][rr * 2 + e] + (e ? wx2[2].y : wx2[2].x);
                float zo = acc[mt][3][rr * 2 + e] + (e ? wx2[3].y : wx2[3].x);
                float ig = sigf(zi), fg = sigf(zf);
                float gg = tanh_(zg), og = sigf(zo);
                float cold = e ? c2.y : c2.x;
                float cc = fg * cold + ig * gg;
                cn[e] = cc;
                hn[e] = og * tanh_(cc);
            }
            *(float2*)&g_c[(size_t)b * HID + jcol] = make_float2(cn[0], cn[1]);

            __half2 phi = __halves2half2(__float2half(hn[0]), __float2half(hn[1]));
            const int reg = rr + 2 * (jw & 1);
            uint32_t idx = (uint32_t)(((grp * 16 + blk_base) * 32 + lane) * 4 + reg);
            Aout[idx] = *(uint32_t*)&phi;

            if (t == SEQ - 1)
                *(float2*)&g_hfin[(size_t)b * HID + jcol] = make_float2(hn[0], hn[1]);
        }
    }
}

// ===========================================================================
// Dense + softmax (reads g_hfin, float)
// ===========================================================================
#define DROWS 8

__global__ __launch_bounds__(128) void dense_softmax_kernel(
    const float* __restrict__ Wd,   // [256, 128]
    const float* __restrict__ bd,   // [128]
    float*       __restrict__ out)  // [BATCH, 128]
{
    const int b0  = blockIdx.x * DROWS;
    const int tid = threadIdx.x;

    __shared__ float hs[DROWS][HID];
    __shared__ float ls[DROWS][VOCAB];

#pragma unroll
    for (int s = 0; s < DROWS * HID / 128; s++) {
        int e = tid + s * 128;
        hs[e >> 8][e & 255] = g_hfin[(size_t)b0 * HID + e];
    }
    __syncthreads();

    float acc[DROWS];
    float bv = bd[tid];
#pragma unroll
    for (int r = 0; r < DROWS; r++) acc[r] = bv;

#pragma unroll 8
    for (int k = 0; k < HID; k++) {
        float w = Wd[k * VOCAB + tid];
#pragma unroll
        for (int r = 0; r < DROWS; r++) acc[r] += hs[r][k] * w;
    }

#pragma unroll
    for (int r = 0; r < DROWS; r++) ls[r][tid] = acc[r];
    __syncthreads();

    const int w = tid >> 5, lane = tid & 31;
#pragma unroll
    for (int rr = 0; rr < 2; rr++) {
        int r = w * 2 + rr;
        float v[4];
        float m = -1e30f;
#pragma unroll
        for (int q = 0; q < 4; q++) {
            v[q] = ls[r][lane + q * 32];
            m = fmaxf(m, v[q]);
        }
#pragma unroll
        for (int o = 16; o > 0; o >>= 1) m = fmaxf(m, __shfl_xor_sync(0xffffffffu, m, o));
        float s = 0.0f;
#pragma unroll
        for (int q = 0; q < 4; q++) {
            v[q] = __expf(v[q] - m);
            s += v[q];
        }
#pragma unroll
        for (int o = 16; o > 0; o >>= 1) s += __shfl_xor_sync(0xffffffffu, s, o);
        float inv = 1.0f / s;
#pragma unroll
        for (int q = 0; q < 4; q++)
            out[(b0 + r) * VOCAB + lane + q * 32] = v[q] * inv;
    }
}

// ===========================================================================
extern "C" void kernel_launch(void* const* d_in, const int* in_sizes, int n_in,
                              void* d_out, int out_size) {
    const int*   inputs = (const int*)d_in[0];
    const float* Wx     = (const float*)d_in[1];
    const float* Wh     = (const float*)d_in[2];
    const float* b      = (const float*)d_in[3];
    const float* Wd     = (const float*)d_in[4];
    const float* bd     = (const float*)d_in[5];
    float*       out    = (float*)d_out;

    cudaFuncSetAttribute(lstm_step_kernel,
                         cudaFuncAttributeMaxDynamicSharedMemorySize, SMEM_TOTAL);

    prep_all_kernel<<<2048, 256>>>(inputs, Wh, Wx, b);

    dim3 grid(BATCH / 64, 8);  // 128 x 8 = 1024 CTAs
    for (int t = 0; t < SEQ; t++)
        lstm_step_kernel<<<grid, 256, SMEM_TOTAL>>>(t);

    dense_softmax_kernel<<<BATCH / DROWS, 128>>>(Wd, bd, out);
}

// round 16
// speedup vs baseline: 1.3629x; 1.2117x over previous
#include <cuda_runtime.h>
#include <cuda_fp16.h>
#include <cstdint>

#define BATCH 8192
#define SEQ   40
#define HID   256
#define VOCAB 128

// ===========================================================================
// Global scratch (no cudaMalloc allowed)
// ===========================================================================
// A fragments (h state, single fp16 plane), ping-pong.
// block = grp*16 + it; grp = batch/16. 32 lanes x uint4.
__device__ __align__(16) uint4 g_Afrag[2][8192][32];
// B fragments (Wh fp16). block = (jt*4+jw)*32 + it*2 + gp.
__device__ __align__(16) uint4 g_Bfrag[1024][32];
__device__ float g_c[BATCH * HID];
__device__ float g_Wxb[128 * 1024];
__device__ float g_hfin[BATCH * HID];
__device__ int   g_inT[SEQ * BATCH];

__device__ __forceinline__ uint32_t smem_to_u32(const void* p) {
    uint32_t a;
    asm("{ .reg .u64 tmp; cvta.to.shared.u64 tmp, %1; cvt.u32.u64 %0, tmp; }"
        : "=r"(a) : "l"(p));
    return a;
}

#define CP_ASYNC16(dst, src) \
    asm volatile("cp.async.cg.shared.global [%0], [%1], 16;" \
        :: "r"(dst), "l"(src) : "memory")
#define CP_COMMIT() asm volatile("cp.async.commit_group;" ::: "memory")
#define CP_WAIT1()  asm volatile("cp.async.wait_group 1;" ::: "memory")
#define CP_WAIT0()  asm volatile("cp.async.wait_group 0;" ::: "memory")

#define LDS128(r0, r1, r2, r3, addr) \
    asm volatile("ld.shared.v4.b32 {%0,%1,%2,%3}, [%4];" \
        : "=r"(r0), "=r"(r1), "=r"(r2), "=r"(r3) : "r"(addr))

#define MMA16816(d, a, b0, b1) \
    asm volatile("mma.sync.aligned.m16n8k16.row.col.f32.f16.f16.f32 " \
        "{%0,%1,%2,%3}, {%4,%5,%6,%7}, {%8,%9}, {%0,%1,%2,%3};" \
        : "+f"((d)[0]), "+f"((d)[1]), "+f"((d)[2]), "+f"((d)[3]) \
        : "r"((a)[0]), "r"((a)[1]), "r"((a)[2]), "r"((a)[3]), \
          "r"(b0), "r"(b1))

__device__ __forceinline__ float tanha(float x) {
    float r;
    asm("tanh.approx.f32 %0, %1;" : "=f"(r) : "f"(x));
    return r;
}
__device__ __forceinline__ float sigf(float x) {
    return fmaf(0.5f, tanha(0.5f * x), 0.5f);
}

__device__ __forceinline__ float sigf_exact(float x) {
    return 1.0f / (1.0f + __expf(-x));
}

// ===========================================================================
// Fused prep: init state + Wh->B frags + Wx+b + input transpose (1 launch)
// ===========================================================================
__global__ void prep_all_kernel(const int*   __restrict__ inputs,
                                const float* __restrict__ Wh,
                                const float* __restrict__ Wx,
                                const float* __restrict__ bias) {
    int i = blockIdx.x * blockDim.x + threadIdx.x;

    ((float4*)g_c)[i] = make_float4(0.f, 0.f, 0.f, 0.f);

    if (i < 262144)
        ((uint4*)g_Afrag[0])[i] = make_uint4(0, 0, 0, 0);

    if (i < 262144) {
        int k = i >> 10, col = i & 1023;
        __half hi = __float2half(Wh[i]);
        int gate = col >> 8, j = col & 255;
        int jt = j >> 5, jw = (j >> 3) & 3, nl = j & 7;
        int kc = k >> 5, ks = (k >> 4) & 1, kk = k & 15;
        int gp = gate >> 1, gs = gate & 1;
        int lane = nl * 4 + ((kk & 7) >> 1);
        int reg  = kk >> 3;
        int hp   = kk & 1;
        int block = (jt * 4 + jw) * 32 + (kc * 2 + ks) * 2 + gp;
        ((__half*)g_Bfrag)[((size_t)block * 32 + lane) * 8 + gs * 4 + reg * 2 + hp] = hi;
    }

    if (i < 131072)
        g_Wxb[i] = Wx[i] + bias[i & 1023];

    if (i < SEQ * BATCH) {
        int b = i / SEQ, tt = i - b * SEQ;
        g_inT[tt * BATCH + b] = inputs[i];
    }
}

// ===========================================================================
// LSTM step (r10 config + split A-wait + HW tanh gates).
// Grid (128, 8); CTA 256 thr = 8 warps (2 mw x 4 jw);
// warp tile M=32 x (4g x 8j). Single-pass fp16. occ 3.
// ===========================================================================
#define SMEM_TOTAL 32768

__global__ __launch_bounds__(256, 3) void lstm_step_kernel(int t) {
    extern __shared__ __align__(16) unsigned char smem[];
    const uint32_t sA = smem_to_u32(smem);
    const int tid  = threadIdx.x;
    const int lane = tid & 31, wid = tid >> 5;
    const int mw = wid >> 2;          // 0..1
    const int jw = wid & 3;           // 0..3
    const int bx = blockIdx.x;        // 0..127
    const int jt = blockIdx.y;        // 0..7

    // ---- stage A tile in TWO commit groups (K halves: it 0-7, 8-15)
    {
        const uint4* Asrc = &g_Afrag[t & 1][bx * 64][0];
#pragma unroll
        for (int half = 0; half < 2; half++) {
#pragma unroll
            for (int i = 0; i < 4; i++) {
                int idx  = tid + i * 256;         // 0..1023
                int grp  = idx >> 8;              // 0..3
                int rest = idx & 255;
                int blk  = grp * 16 + half * 8 + (rest >> 5);
                int u    = rest & 31;
                CP_ASYNC16(sA + blk * 512 + u * 16,
                           (const char*)(Asrc + blk * 32 + u));
            }
            CP_COMMIT();
        }
    }

    // ---- prefetch chars while A streams
    const int gq = lane >> 2, t4 = lane & 3;
    int ch[2][2];
#pragma unroll
    for (int mt = 0; mt < 2; mt++)
#pragma unroll
        for (int rr = 0; rr < 2; rr++)
            ch[mt][rr] = g_inT[t * BATCH + bx * 64 + mw * 32 + mt * 16 + gq + rr * 8];

    // ---- prefetch B iter 0 (2 blocks: gate pairs)
    const uint4* __restrict__ Bp = &g_Bfrag[(jt * 4 + jw) * 32][lane];
    uint4 bv0 = Bp[0], bv1 = Bp[32];

    CP_WAIT1();          // first K-half landed; second still streaming
    __syncthreads();

    float acc[2][4][4];
#pragma unroll
    for (int mt = 0; mt < 2; mt++)
#pragma unroll
        for (int g = 0; g < 4; g++)
#pragma unroll
            for (int e = 0; e < 4; e++) acc[mt][g][e] = 0.0f;

    const uint32_t aoff0 = sA + (mw * 2 + 0) * 16 * 512 + lane * 16;
    const uint32_t aoff1 = sA + (mw * 2 + 1) * 16 * 512 + lane * 16;

#pragma unroll 4
    for (int it = 0; it < 8; it++) {
        uint4 bn0, bn1;
        {
            const uint4* p = Bp + (it + 1) * 64;
            bn0 = p[0]; bn1 = p[32];
        }
        uint32_t ah[2][4];
        {
            uint32_t o = it * 512;
            LDS128(ah[0][0], ah[0][1], ah[0][2], ah[0][3], aoff0 + o);
            LDS128(ah[1][0], ah[1][1], ah[1][2], ah[1][3], aoff1 + o);
        }
#pragma unroll
        for (int mt = 0; mt < 2; mt++) {
            MMA16816(acc[mt][0], ah[mt], bv0.x, bv0.y);
            MMA16816(acc[mt][1], ah[mt], bv0.z, bv0.w);
            MMA16816(acc[mt][2], ah[mt], bv1.x, bv1.y);
            MMA16816(acc[mt][3], ah[mt], bv1.z, bv1.w);
        }
        bv0 = bn0; bv1 = bn1;
    }

    CP_WAIT0();          // second K-half landed
    __syncthreads();

#pragma unroll 4
    for (int it = 8; it < 16; it++) {
        uint4 bn0, bn1;
        if (it < 15) {
            const uint4* p = Bp + (it + 1) * 64;
            bn0 = p[0]; bn1 = p[32];
        } else {
            bn0 = bv0; bn1 = bv1;
        }
        uint32_t ah[2][4];
        {
            uint32_t o = it * 512;
            LDS128(ah[0][0], ah[0][1], ah[0][2], ah[0][3], aoff0 + o);
            LDS128(ah[1][0], ah[1][1], ah[1][2], ah[1][3], aoff1 + o);
        }
#pragma unroll
        for (int mt = 0; mt < 2; mt++) {
            MMA16816(acc[mt][0], ah[mt], bv0.x, bv0.y);
            MMA16816(acc[mt][1], ah[mt], bv0.z, bv0.w);
            MMA16816(acc[mt][2], ah[mt], bv1.x, bv1.y);
            MMA16816(acc[mt][3], ah[mt], bv1.z, bv1.w);
        }
        bv0 = bn0; bv1 = bn1;
    }

    // ---- Epilogue: z = acc + Wxb[char] -> gates (HW tanh) -> c; h as A-frags.
    const int jcol = jt * 32 + jw * 8 + t4 * 2;   // even
    const int blk_base = jt * 2 + (jw >> 1);
    uint32_t* __restrict__ Aout = (uint32_t*)g_Afrag[(t + 1) & 1];

#pragma unroll
    for (int mt = 0; mt < 2; mt++) {
        const int grp = bx * 4 + mw * 2 + mt;
#pragma unroll
        for (int rr = 0; rr < 2; rr++) {
            const int b = bx * 64 + mw * 32 + mt * 16 + gq + rr * 8;
            const float* wrow = g_Wxb + (size_t)ch[mt][rr] * 1024;
            float2 wx2[4];
#pragma unroll
            for (int g = 0; g < 4; g++)
                wx2[g] = *(const float2*)&wrow[g * 256 + jcol];
            float2 c2 = *(const float2*)&g_c[(size_t)b * HID + jcol];

            float cn[2], hn[2];
#pragma unroll
            for (int e = 0; e < 2; e++) {
                float zi = acc[mt][0][rr * 2 + e] + (e ? wx2[0].y : wx2[0].x);
                float zf = acc[mt][1][rr * 2 + e] + (e ? wx2[1].y : wx2[1].x);
                float zg = acc[mt][2][rr * 2 + e] + (e ? wx2[2].y : wx2[2].x);
                float zo = acc[mt][3][rr * 2 + e] + (e ? wx2[3].y : wx2[3].x);
                float ig = sigf(zi), fg = sigf(zf);
                float gg = tanha(zg), og = sigf(zo);
                float cold = e ? c2.y : c2.x;
                float cc = fg * cold + ig * gg;
                cn[e] = cc;
                hn[e] = og * tanha(cc);
            }
            *(float2*)&g_c[(size_t)b * HID + jcol] = make_float2(cn[0], cn[1]);

            __half2 phi = __halves2half2(__float2half(hn[0]), __float2half(hn[1]));
            const int reg = rr + 2 * (jw & 1);
            uint32_t idx = (uint32_t)(((grp * 16 + blk_base) * 32 + lane) * 4 + reg);
            Aout[idx] = *(uint32_t*)&phi;

            if (t == SEQ - 1)
                *(float2*)&g_hfin[(size_t)b * HID + jcol] = make_float2(hn[0], hn[1]);
        }
    }
}

// ===========================================================================
// Dense + softmax (reads g_hfin, float)
// ===========================================================================
#define DROWS 8

__global__ __launch_bounds__(128) void dense_softmax_kernel(
    const float* __restrict__ Wd,   // [256, 128]
    const float* __restrict__ bd,   // [128]
    float*       __restrict__ out)  // [BATCH, 128]
{
    const int b0  = blockIdx.x * DROWS;
    const int tid = threadIdx.x;

    __shared__ float hs[DROWS][HID];
    __shared__ float ls[DROWS][VOCAB];

#pragma unroll
    for (int s = 0; s < DROWS * HID / 128; s++) {
        int e = tid + s * 128;
        hs[e >> 8][e & 255] = g_hfin[(size_t)b0 * HID + e];
    }
    __syncthreads();

    float acc[DROWS];
    float bv = bd[tid];
#pragma unroll
    for (int r = 0; r < DROWS; r++) acc[r] = bv;

#pragma unroll 8
    for (int k = 0; k < HID; k++) {
        float w = Wd[k * VOCAB + tid];
#pragma unroll
        for (int r = 0; r < DROWS; r++) acc[r] += hs[r][k] * w;
    }

#pragma unroll
    for (int r = 0; r < DROWS; r++) ls[r][tid] = acc[r];
    __syncthreads();

    const int w = tid >> 5, lane = tid & 31;
#pragma unroll
    for (int rr = 0; rr < 2; rr++) {
        int r = w * 2 + rr;
        float v[4];
        float m = -1e30f;
#pragma unroll
        for (int q = 0; q < 4; q++) {
            v[q] = ls[r][lane + q * 32];
            m = fmaxf(m, v[q]);
        }
#pragma unroll
        for (int o = 16; o > 0; o >>= 1) m = fmaxf(m, __shfl_xor_sync(0xffffffffu, m, o));
        float s = 0.0f;
#pragma unroll
        for (int q = 0; q < 4; q++) {
            v[q] = __expf(v[q] - m);
            s += v[q];
        }
#pragma unroll
        for (int o = 16; o > 0; o >>= 1) s += __shfl_xor_sync(0xffffffffu, s, o);
        float inv = 1.0f / s;
#pragma unroll
        for (int q = 0; q < 4; q++)
            out[(b0 + r) * VOCAB + lane + q * 32] = v[q] * inv;
    }
}

// ===========================================================================
extern "C" void kernel_launch(void* const* d_in, const int* in_sizes, int n_in,
                              void* d_out, int out_size) {
    const int*   inputs = (const int*)d_in[0];
    const float* Wx     = (const float*)d_in[1];
    const float* Wh     = (const float*)d_in[2];
    const float* b      = (const float*)d_in[3];
    const float* Wd     = (const float*)d_in[4];
    const float* bd     = (const float*)d_in[5];
    float*       out    = (float*)d_out;

    cudaFuncSetAttribute(lstm_step_kernel,
                         cudaFuncAttributeMaxDynamicSharedMemorySize, SMEM_TOTAL);

    prep_all_kernel<<<2048, 256>>>(inputs, Wh, Wx, b);

    dim3 grid(BATCH / 64, 8);  // 128 x 8 = 1024 CTAs
    for (int t = 0; t < SEQ; t++)
        lstm_step_kernel<<<grid, 256, SMEM_TOTAL>>>(t);

    dense_softmax_kernel<<<BATCH / DROWS, 128>>>(Wd, bd, out);
}

// round 17
// speedup vs baseline: 1.5735x; 1.1546x over previous
#include <cuda_runtime.h>
#include <cuda_fp16.h>
#include <cstdint>

#define BATCH 8192
#define SEQ   40
#define HID   256
#define VOCAB 128

#define MB    64          // batch rows per CTA
#define NCTA  (BATCH/MB)  // 128
#define NT    512         // threads per CTA (16 warps)

// ===========================================================================
// Global scratch (no cudaMalloc allowed)
// ===========================================================================
// B fragments (Wh fp16). block = (jt*4+jw)*32 + it*2 + gp. 32 lanes x uint4.
__device__ __align__(16) uint4 g_Bfrag[1024][32];
__device__ float g_Wxb[128 * 1024];     // Wx + bias folded
__device__ float g_hfin[BATCH * HID];   // final h for dense kernel
__device__ int   g_inT[SEQ * BATCH];    // transposed chars [t][b]

__device__ __forceinline__ uint32_t smem_to_u32(const void* p) {
    uint32_t a;
    asm("{ .reg .u64 tmp; cvta.to.shared.u64 tmp, %1; cvt.u32.u64 %0, tmp; }"
        : "=r"(a) : "l"(p));
    return a;
}

#define LDS128(r0, r1, r2, r3, addr) \
    asm volatile("ld.shared.v4.b32 {%0,%1,%2,%3}, [%4];" \
        : "=r"(r0), "=r"(r1), "=r"(r2), "=r"(r3) : "r"(addr))

#define MMA16816(d, a, b0, b1) \
    asm volatile("mma.sync.aligned.m16n8k16.row.col.f32.f16.f16.f32 " \
        "{%0,%1,%2,%3}, {%4,%5,%6,%7}, {%8,%9}, {%0,%1,%2,%3};" \
        : "+f"((d)[0]), "+f"((d)[1]), "+f"((d)[2]), "+f"((d)[3]) \
        : "r"((a)[0]), "r"((a)[1]), "r"((a)[2]), "r"((a)[3]), \
          "r"(b0), "r"(b1))

__device__ __forceinline__ float tanha(float x) {
    float r;
    asm("tanh.approx.f32 %0, %1;" : "=f"(r) : "f"(x));
    return r;
}
__device__ __forceinline__ float sigf(float x) {
    return fmaf(0.5f, tanha(0.5f * x), 0.5f);
}

// ===========================================================================
// Fused prep: Wh->B frags + Wx+b + input transpose (1 launch, 1280x256)
// ===========================================================================
__global__ void prep_all_kernel(const int*   __restrict__ inputs,
                                const float* __restrict__ Wh,
                                const float* __restrict__ Wx,
                                const float* __restrict__ bias) {
    int i = blockIdx.x * blockDim.x + threadIdx.x;   // 0 .. 327679

    if (i < 262144) {
        int k = i >> 10, col = i & 1023;
        __half hi = __float2half(Wh[i]);
        int gate = col >> 8, j = col & 255;
        int jt = j >> 5, jw = (j >> 3) & 3, nl = j & 7;
        int kc = k >> 5, ks = (k >> 4) & 1, kk = k & 15;
        int gp = gate >> 1, gs = gate & 1;
        int lane = nl * 4 + ((kk & 7) >> 1);
        int reg  = kk >> 3;
        int hp   = kk & 1;
        int block = (jt * 4 + jw) * 32 + (kc * 2 + ks) * 2 + gp;
        ((__half*)g_Bfrag)[((size_t)block * 32 + lane) * 8 + gs * 4 + reg * 2 + hp] = hi;
    }

    if (i < 131072)
        g_Wxb[i] = Wx[i] + bias[i & 1023];

    if (i < SEQ * BATCH) {
        int b = i / SEQ, tt = i - b * SEQ;
        g_inT[tt * BATCH + b] = inputs[i];
    }
}

// ===========================================================================
// Persistent per-batch-tile LSTM: batch rows are independent chains, so each
// CTA owns 64 rows x full hidden width and runs all 40 steps with h ping-pong
// and c entirely in SMEM. No grid syncs, no A gmem traffic, one launch.
//
// 16 warps: mw(2) x jth(2) x jw(4). Per step: 4 jtp iters (jt = jtp*2+jth);
// warp tile M=32 (mt 2x16) x (4 gates x 8 j) — acc 32 regs, B reg prefetch
// depth 2. Epilogue: Wxb gather + c(SMEM) -> gates(HW tanh) -> h STS in
// A-frag layout. One __syncthreads per step.
//
// SMEM: h buf0 [0,32KB), h buf1 [32KB,64KB), c [64KB, 64KB+66560).
// ===========================================================================
#define SM_C      65536
#define C_STRIDE  260                       // floats; 2-way max bank conflict
#define SMEM_TOTAL (65536 + MB * C_STRIDE * 4)   // 132096

__global__ __launch_bounds__(NT, 1) void lstm_persist_kernel() {
    extern __shared__ __align__(16) unsigned char smem[];
    const uint32_t sbase = smem_to_u32(smem);
    const int tid  = threadIdx.x;
    const int lane = tid & 31, wid = tid >> 5;
    const int jw  = wid & 3;
    const int jth = (wid >> 2) & 1;
    const int mw  = wid >> 3;          // 0..1
    const int bx  = blockIdx.x;        // 0..127
    const int gq = lane >> 2, t4 = lane & 3;

    // ---- zero h buffers + c
    for (int i = tid; i < SMEM_TOTAL / 16; i += NT)
        ((uint4*)smem)[i] = make_uint4(0, 0, 0, 0);
    __syncthreads();

#pragma unroll 1
    for (int t = 0; t < SEQ; t++) {
        const uint32_t cur = sbase + (t & 1) * 32768;
        const uint32_t nxtoff = ((t + 1) & 1) * 32768;

        // chars for this step (same for all jtp)
        int ch[2][2];
#pragma unroll
        for (int mt = 0; mt < 2; mt++)
#pragma unroll
            for (int rr = 0; rr < 2; rr++)
                ch[mt][rr] = g_inT[t * BATCH + bx * MB + mw * 32 + mt * 16
                                   + gq + rr * 8];

#pragma unroll 1
        for (int jtp = 0; jtp < 4; jtp++) {
            const int jt = jtp * 2 + jth;
            const uint4* __restrict__ Bp = &g_Bfrag[(jt * 4 + jw) * 32][lane];
            uint4 bv0 = Bp[0],  bv1 = Bp[32];
            uint4 bn0 = Bp[64], bn1 = Bp[96];

            float acc[2][4][4];
#pragma unroll
            for (int mt = 0; mt < 2; mt++)
#pragma unroll
                for (int g = 0; g < 4; g++)
#pragma unroll
                    for (int e = 0; e < 4; e++) acc[mt][g][e] = 0.0f;

            const uint32_t aoff0 = cur + (mw * 2 + 0) * 8192 + lane * 16;
            const uint32_t aoff1 = cur + (mw * 2 + 1) * 8192 + lane * 16;

#pragma unroll 4
            for (int it = 0; it < 16; it++) {
                uint4 bf0, bf1;
                if (it < 14) {
                    const uint4* p = Bp + (it + 2) * 64;
                    bf0 = p[0]; bf1 = p[32];
                } else {
                    bf0 = bn0; bf1 = bn1;
                }

                uint32_t ah[2][4];
                {
                    uint32_t o = it * 512;
                    LDS128(ah[0][0], ah[0][1], ah[0][2], ah[0][3], aoff0 + o);
                    LDS128(ah[1][0], ah[1][1], ah[1][2], ah[1][3], aoff1 + o);
                }

#pragma unroll
                for (int mt = 0; mt < 2; mt++) {
                    MMA16816(acc[mt][0], ah[mt], bv0.x, bv0.y);
                    MMA16816(acc[mt][1], ah[mt], bv0.z, bv0.w);
                    MMA16816(acc[mt][2], ah[mt], bv1.x, bv1.y);
                    MMA16816(acc[mt][3], ah[mt], bv1.z, bv1.w);
                }
                bv0 = bn0; bv1 = bn1; bn0 = bf0; bn1 = bf1;
            }

            // ---- epilogue for this jt slice
            const int jcol = jt * 32 + jw * 8 + t4 * 2;   // even
            const int blk  = jt * 2 + (jw >> 1);

#pragma unroll
            for (int mt = 0; mt < 2; mt++) {
                uint32_t phi2[2];
#pragma unroll
                for (int rr = 0; rr < 2; rr++) {
                    const int bl = mw * 32 + mt * 16 + gq + rr * 8;  // 0..63
                    const float* wrow = g_Wxb + (size_t)ch[mt][rr] * 1024;
                    float2 wx2[4];
#pragma unroll
                    for (int g = 0; g < 4; g++)
                        wx2[g] = *(const float2*)&wrow[g * 256 + jcol];

                    float2* cp = (float2*)(smem + SM_C
                                           + ((size_t)bl * C_STRIDE + jcol) * 4);
                    float2 c2 = *cp;

                    float cn[2], hn[2];
#pragma unroll
                    for (int e = 0; e < 2; e++) {
                        float zi = acc[mt][0][rr * 2 + e] + (e ? wx2[0].y : wx2[0].x);
                        float zf = acc[mt][1][rr * 2 + e] + (e ? wx2[1].y : wx2[1].x);
                        float zg = acc[mt][2][rr * 2 + e] + (e ? wx2[2].y : wx2[2].x);
                        float zo = acc[mt][3][rr * 2 + e] + (e ? wx2[3].y : wx2[3].x);
                        float ig = sigf(zi), fg = sigf(zf);
                        float gg = tanha(zg), og = sigf(zo);
                        float cold = e ? c2.y : c2.x;
                        float cc = fg * cold + ig * gg;
                        cn[e] = cc;
                        hn[e] = og * tanha(cc);
                    }
                    *cp = make_float2(cn[0], cn[1]);

                    __half2 phi = __halves2half2(__float2half(hn[0]),
                                                 __float2half(hn[1]));
                    phi2[rr] = *(uint32_t*)&phi;

                    if (t == SEQ - 1)
                        *(float2*)&g_hfin[(size_t)(bx * MB + bl) * HID + jcol] =
                            make_float2(hn[0], hn[1]);
                }
                // store h(t+1) frag: regs (rr=0,1) at base 2*(jw&1) — one uint2
                const int grp = mw * 2 + mt;
                *(uint2*)(smem + nxtoff
                          + ((grp * 16 + blk) * 32 + lane) * 16
                          + (jw & 1) * 8) = make_uint2(phi2[0], phi2[1]);
            }
        }

        __syncthreads();   // h(t+1) complete before next step reads it
    }
}

// ===========================================================================
// Dense + softmax (reads g_hfin, float)
// ===========================================================================
#define DROWS 8

__global__ __launch_bounds__(128) void dense_softmax_kernel(
    const float* __restrict__ Wd,   // [256, 128]
    const float* __restrict__ bd,   // [128]
    float*       __restrict__ out)  // [BATCH, 128]
{
    const int b0  = blockIdx.x * DROWS;
    const int tid = threadIdx.x;

    __shared__ float hs[DROWS][HID];
    __shared__ float ls[DROWS][VOCAB];

#pragma unroll
    for (int s = 0; s < DROWS * HID / 128; s++) {
        int e = tid + s * 128;
        hs[e >> 8][e & 255] = g_hfin[(size_t)b0 * HID + e];
    }
    __syncthreads();

    float acc[DROWS];
    float bv = bd[tid];
#pragma unroll
    for (int r = 0; r < DROWS; r++) acc[r] = bv;

#pragma unroll 8
    for (int k = 0; k < HID; k++) {
        float w = Wd[k * VOCAB + tid];
#pragma unroll
        for (int r = 0; r < DROWS; r++) acc[r] += hs[r][k] * w;
    }

#pragma unroll
    for (int r = 0; r < DROWS; r++) ls[r][tid] = acc[r];
    __syncthreads();

    const int w = tid >> 5, lane = tid & 31;
#pragma unroll
    for (int rr = 0; rr < 2; rr++) {
        int r = w * 2 + rr;
        float v[4];
        float m = -1e30f;
#pragma unroll
        for (int q = 0; q < 4; q++) {
            v[q] = ls[r][lane + q * 32];
            m = fmaxf(m, v[q]);
        }
#pragma unroll
        for (int o = 16; o > 0; o >>= 1) m = fmaxf(m, __shfl_xor_sync(0xffffffffu, m, o));
        float s = 0.0f;
#pragma unroll
        for (int q = 0; q < 4; q++) {
            v[q] = __expf(v[q] - m);
            s += v[q];
        }
#pragma unroll
        for (int o = 16; o > 0; o >>= 1) s += __shfl_xor_sync(0xffffffffu, s, o);
        float inv = 1.0f / s;
#pragma unroll
        for (int q = 0; q < 4; q++)
            out[(b0 + r) * VOCAB + lane + q * 32] = v[q] * inv;
    }
}

// ===========================================================================
extern "C" void kernel_launch(void* const* d_in, const int* in_sizes, int n_in,
                              void* d_out, int out_size) {
    const int*   inputs = (const int*)d_in[0];
    const float* Wx     = (const float*)d_in[1];
    const float* Wh     = (const float*)d_in[2];
    const float* b      = (const float*)d_in[3];
    const float* Wd     = (const float*)d_in[4];
    const float* bd     = (const float*)d_in[5];
    float*       out    = (float*)d_out;

    cudaFuncSetAttribute(lstm_persist_kernel,
                         cudaFuncAttributeMaxDynamicSharedMemorySize, SMEM_TOTAL);

    prep_all_kernel<<<1280, 256>>>(inputs, Wh, Wx, b);

    lstm_persist_kernel<<<NCTA, NT, SMEM_TOTAL>>>();

    dense_softmax_kernel<<<BATCH / DROWS, 128>>>(Wd, bd, out);
}